// round 1
// baseline (speedup 1.0000x reference)
#include <cuda_runtime.h>

// Problem constants (fixed by setup_inputs)
#define NUM_CLASSES 19
#define BATCH 16
#define HH 1024
#define WW 2048
#define GSZ 8
#define HB (HH / GSZ)            // 128
#define WB (WW / GSZ)            // 256
#define NBLOCKS (BATCH * HB * WB) // 524288
#define TPB 256
#define NCTA (NBLOCKS / TPB)      // 2048

// CTA partial sums (allocation-free scratch; every CTA overwrites its own
// slot each launch -> deterministic, graph-capturable)
__device__ float g_partials[NCTA];

__global__ void __launch_bounds__(TPB)
fsenc_loss_kernel(const float* __restrict__ preds,
                  const int* __restrict__ targets)
{
    const int tile = blockIdx.x * TPB + threadIdx.x;   // [0, NBLOCKS)

    // tile -> (b, hb, wb): row-major over (BATCH, HB, WB)
    const int wb = tile & (WB - 1);
    const int t2 = tile >> 8;        // / WB (WB=256)
    const int hb = t2 & (HB - 1);
    const int b  = t2 >> 7;          // / HB (HB=128)

    const int* tbase = targets + ((size_t)b * HH + (size_t)hb * GSZ) * WW
                               + (size_t)wb * GSZ;

    // Build 19-bit presence mask over the 8x8 tile.
    unsigned mask = 0u;
    #pragma unroll
    for (int r = 0; r < GSZ; r++) {
        const int4* p = reinterpret_cast<const int4*>(tbase + (size_t)r * WW);
        int4 a = __ldg(p);
        int4 c = __ldg(p + 1);
        mask |= (1u << a.x) | (1u << a.y) | (1u << a.z) | (1u << a.w);
        mask |= (1u << c.x) | (1u << c.y) | (1u << c.z) | (1u << c.w);
    }

    // loss_c = softplus(x_c) - present_c * x_c
    const float* prow = preds + (size_t)tile * NUM_CLASSES;
    float s = 0.0f;
    #pragma unroll
    for (int c = 0; c < NUM_CLASSES; c++) {
        float x  = __ldg(prow + c);
        float sp = fmaxf(x, 0.0f) + __logf(1.0f + __expf(-fabsf(x)));
        s += sp - (((mask >> c) & 1u) ? x : 0.0f);
    }

    // Warp reduce
    #pragma unroll
    for (int o = 16; o > 0; o >>= 1)
        s += __shfl_xor_sync(0xffffffffu, s, o);

    __shared__ float sm[TPB / 32];
    if ((threadIdx.x & 31) == 0)
        sm[threadIdx.x >> 5] = s;
    __syncthreads();

    if (threadIdx.x == 0) {
        float v = 0.0f;
        #pragma unroll
        for (int i = 0; i < TPB / 32; i++)
            v += sm[i];
        g_partials[blockIdx.x] = v;
    }
}

__global__ void __launch_bounds__(256)
fsenc_reduce_kernel(float* __restrict__ out)
{
    __shared__ double sm[256];
    double s = 0.0;
    for (int i = threadIdx.x; i < NCTA; i += 256)
        s += (double)g_partials[i];
    sm[threadIdx.x] = s;
    __syncthreads();
    #pragma unroll
    for (int stride = 128; stride > 0; stride >>= 1) {
        if (threadIdx.x < stride)
            sm[threadIdx.x] += sm[threadIdx.x + stride];
        __syncthreads();
    }
    if (threadIdx.x == 0)
        out[0] = (float)(sm[0] / ((double)NBLOCKS * (double)NUM_CLASSES));
}

extern "C" void kernel_launch(void* const* d_in, const int* in_sizes, int n_in,
                              void* d_out, int out_size)
{
    const float* preds   = (const float*)d_in[0];
    const int*   targets = (const int*)d_in[1];
    // d_in[2] = grid_size (known constant 8)

    fsenc_loss_kernel<<<NCTA, TPB>>>(preds, targets);
    fsenc_reduce_kernel<<<1, 256>>>((float*)d_out);
}

// round 2
// speedup vs baseline: 1.0589x; 1.0589x over previous
#include <cuda_runtime.h>

// Problem constants (fixed by setup_inputs)
#define NUM_CLASSES 19
#define BATCH 16
#define HH 1024
#define WW 2048
#define GSZ 8
#define HB (HH / GSZ)             // 128
#define WB (WW / GSZ)             // 256
#define NBLOCKS (BATCH * HB * WB) // 524288
#define TPB 256
#define NCTA (NBLOCKS / TPB)      // 2048
#define WARPS (TPB / 32)
#define ROWF (32 * NUM_CLASSES)   // 608 floats per warp stage

// Allocation-free scratch. g_count is reset to 0 by the last block each
// launch, so every graph replay sees a clean counter (deterministic).
__device__ float g_partials[NCTA];
__device__ unsigned g_count = 0;

__global__ void __launch_bounds__(TPB)
fsenc_fused_kernel(const float* __restrict__ preds,
                   const int* __restrict__ targets,
                   float* __restrict__ out)
{
    __shared__ float sp[WARPS][ROWF];   // 19456 B pred staging
    __shared__ float warpsum[WARPS];
    __shared__ double dsm[TPB];
    __shared__ bool isLast;

    const int tid  = threadIdx.x;
    const int w    = tid >> 5;
    const int lane = tid & 31;
    const int tileBase = blockIdx.x * TPB + (w << 5);
    const int tile     = tileBase + lane;

    // ---- Stage this warp's 32 pred rows (2432 contiguous bytes) ----
    // 152 float4 loads, fully coalesced, high MLP.
    const float4* psrc =
        reinterpret_cast<const float4*>(preds + (size_t)tileBase * NUM_CLASSES);
    float4* pdst = reinterpret_cast<float4*>(sp[w]);
    #pragma unroll
    for (int i = 0; i < 5; i++) {
        int idx = lane + i * 32;
        if (idx < ROWF / 4) pdst[idx] = __ldg(psrc + idx);
    }

    // ---- Build 19-bit presence mask over the 8x8 target tile ----
    const int wb = tile & (WB - 1);
    const int t2 = tile >> 8;           // / WB
    const int hb = t2 & (HB - 1);
    const int b  = t2 >> 7;             // / HB
    const int* tbase = targets + ((size_t)b * HH + (size_t)hb * GSZ) * WW
                               + (size_t)wb * GSZ;
    unsigned mask = 0u;
    #pragma unroll
    for (int r = 0; r < GSZ; r++) {
        const int4* p = reinterpret_cast<const int4*>(tbase + (size_t)r * WW);
        int4 a = __ldg(p);
        int4 c = __ldg(p + 1);
        mask |= (1u << a.x) | (1u << a.y) | (1u << a.z) | (1u << a.w);
        mask |= (1u << c.x) | (1u << c.y) | (1u << c.z) | (1u << c.w);
    }

    __syncwarp();

    // ---- loss_c = softplus(x_c) - present_c * x_c ----
    // smem read at stride 19: gcd(19,32)=1 -> bank-conflict-free.
    const float* row = sp[w] + lane * NUM_CLASSES;
    float s = 0.0f;
    #pragma unroll
    for (int c = 0; c < NUM_CLASSES; c++) {
        float x  = row[c];
        float sv = fmaxf(x, 0.0f) + __logf(1.0f + __expf(-fabsf(x)));
        s += sv - (((mask >> c) & 1u) ? x : 0.0f);
    }

    // ---- Block reduce ----
    #pragma unroll
    for (int o = 16; o > 0; o >>= 1)
        s += __shfl_xor_sync(0xffffffffu, s, o);
    if (lane == 0) warpsum[w] = s;
    __syncthreads();

    if (tid == 0) {
        float v = 0.0f;
        #pragma unroll
        for (int i = 0; i < WARPS; i++) v += warpsum[i];
        g_partials[blockIdx.x] = v;
        __threadfence();
        unsigned n = atomicAdd(&g_count, 1u);
        isLast = (n == NCTA - 1);
    }
    __syncthreads();

    // ---- Last block: deterministic final reduce + mean ----
    if (isLast) {
        double d = 0.0;
        for (int i = tid; i < NCTA; i += TPB)
            d += (double)__ldcg(&g_partials[i]);
        dsm[tid] = d;
        __syncthreads();
        #pragma unroll
        for (int st = TPB / 2; st > 0; st >>= 1) {
            if (tid < st) dsm[tid] += dsm[tid + st];
            __syncthreads();
        }
        if (tid == 0) {
            out[0] = (float)(dsm[0] / ((double)NBLOCKS * (double)NUM_CLASSES));
            g_count = 0;   // reset for next graph replay
        }
    }
}

extern "C" void kernel_launch(void* const* d_in, const int* in_sizes, int n_in,
                              void* d_out, int out_size)
{
    const float* preds   = (const float*)d_in[0];
    const int*   targets = (const int*)d_in[1];
    // d_in[2] = grid_size (known constant 8)

    fsenc_fused_kernel<<<NCTA, TPB>>>(preds, targets, (float*)d_out);
}

// round 3
// speedup vs baseline: 1.1231x; 1.0606x over previous
#include <cuda_runtime.h>

// Problem constants (fixed by setup_inputs)
#define NUM_CLASSES 19
#define BATCH 16
#define HH 1024
#define WW 2048
#define GSZ 8
#define HB (HH / GSZ)             // 128
#define WB (WW / GSZ)             // 256
#define NBLOCKS (BATCH * HB * WB) // 524288
#define TPB 256
#define NCTA (NBLOCKS / TPB)      // 2048
#define WARPS (TPB / 32)

// Allocation-free scratch. g_count is reset to 0 by the last block each
// launch, so every graph replay sees a clean counter (deterministic).
__device__ float g_partials[NCTA];
__device__ unsigned g_count = 0;

__global__ void __launch_bounds__(TPB)
fsenc_fused_kernel(const float* __restrict__ preds,
                   const int* __restrict__ targets,
                   float* __restrict__ out)
{
    __shared__ float warpsum[WARPS];
    __shared__ double dsm[TPB];
    __shared__ bool isLast;

    const int tid  = threadIdx.x;
    const int w    = tid >> 5;
    const int lane = tid & 31;
    const int tile = blockIdx.x * TPB + tid;   // [0, NBLOCKS)

    // tile -> (b, hb, wb): row-major over (BATCH, HB, WB)
    const int wb = tile & (WB - 1);
    const int t2 = tile >> 8;           // / WB (WB=256)
    const int hb = t2 & (HB - 1);
    const int b  = t2 >> 7;             // / HB (HB=128)

    const int* tbase = targets + ((size_t)b * HH + (size_t)hb * GSZ) * WW
                               + (size_t)wb * GSZ;

    // ---- Build 19-bit presence mask over the 8x8 target tile ----
    // Streaming data, touched once: evict-first.
    unsigned mask = 0u;
    #pragma unroll
    for (int r = 0; r < GSZ; r++) {
        const int4* p = reinterpret_cast<const int4*>(tbase + (size_t)r * WW);
        int4 a = __ldcs(p);
        int4 c = __ldcs(p + 1);
        mask |= (1u << a.x) | (1u << a.y) | (1u << a.z) | (1u << a.w);
        mask |= (1u << c.x) | (1u << c.y) | (1u << c.z) | (1u << c.w);
    }

    // ---- loss_c = softplus(x_c) - present_c * x_c ----
    const float* prow = preds + (size_t)tile * NUM_CLASSES;
    float s = 0.0f;
    #pragma unroll
    for (int c = 0; c < NUM_CLASSES; c++) {
        float x  = __ldg(prow + c);
        float sv = fmaxf(x, 0.0f) + __logf(1.0f + __expf(-fabsf(x)));
        s += sv - (((mask >> c) & 1u) ? x : 0.0f);
    }

    // ---- Block reduce ----
    #pragma unroll
    for (int o = 16; o > 0; o >>= 1)
        s += __shfl_xor_sync(0xffffffffu, s, o);
    if (lane == 0) warpsum[w] = s;
    __syncthreads();

    if (tid == 0) {
        float v = 0.0f;
        #pragma unroll
        for (int i = 0; i < WARPS; i++) v += warpsum[i];
        g_partials[blockIdx.x] = v;
        __threadfence();
        unsigned n = atomicAdd(&g_count, 1u);
        isLast = (n == NCTA - 1);
    }
    __syncthreads();

    // ---- Last block: deterministic final reduce + mean ----
    if (isLast) {
        double d = 0.0;
        for (int i = tid; i < NCTA; i += TPB)
            d += (double)__ldcg(&g_partials[i]);
        dsm[tid] = d;
        __syncthreads();
        #pragma unroll
        for (int st = TPB / 2; st > 0; st >>= 1) {
            if (tid < st) dsm[tid] += dsm[tid + st];
            __syncthreads();
        }
        if (tid == 0) {
            out[0] = (float)(dsm[0] / ((double)NBLOCKS * (double)NUM_CLASSES));
            g_count = 0;   // reset for next graph replay
        }
    }
}

extern "C" void kernel_launch(void* const* d_in, const int* in_sizes, int n_in,
                              void* d_out, int out_size)
{
    const float* preds   = (const float*)d_in[0];
    const int*   targets = (const int*)d_in[1];
    // d_in[2] = grid_size (known constant 8)

    fsenc_fused_kernel<<<NCTA, TPB>>>(preds, targets, (float*)d_out);
}